// round 5
// baseline (speedup 1.0000x reference)
#include <cuda_runtime.h>
#include <math.h>

// Shapes (fixed by the problem)
#define BATCH 4
#define CHN   32
#define HDIM  256
#define WDIM  256
#define PLANE (HDIM * WDIM)           // 65536
#define NPIX  (BATCH * PLANE)         // 262144
#define NROWS (BATCH * CHN * HDIM)    // 32768 rows (W pass)
#define NEL   (BATCH * CHN * PLANE)   // 8388608 complex elements

// ---------- global scratch / tables (static device memory only) ----------
__device__ float4 g_scratch4[NEL / 2];          // 8388608 float2 viewed as float4 (16B aligned)
__device__ float2 g_c1[256];
__device__ float2 g_c2[256];
__device__ float2 g_w256[256];                  // exp(-2*pi*i*m/256)
__device__ float  g_scale;

// ---------- complex helpers ----------
static __device__ __forceinline__ float2 cmul(float2 a, float2 b) {
    return make_float2(fmaf(a.x, b.x, -(a.y * b.y)), fmaf(a.x, b.y, a.y * b.x));
}
static __device__ __forceinline__ float2 cadd(float2 a, float2 b) {
    return make_float2(a.x + b.x, a.y + b.y);
}
static __device__ __forceinline__ float2 csub(float2 a, float2 b) {
    return make_float2(a.x - b.x, a.y - b.y);
}

// ---------- register DFT-16: DIF radix-2, natural in, bit-reversed out ----------
// sign S = -1: out[j] = sum_n x[n] exp(-2*pi*i*n*brev4(j)/16)
// sign S = +1: conjugated twiddles (inverse-direction DFT, no 1/N)
template <int S>
static __device__ __forceinline__ void fft16(float2* r) {
    const float sg = (float)S;
    const float C16[8] = {1.0f, 0.923879533f, 0.707106781f, 0.382683432f,
                          0.0f, -0.382683432f, -0.707106781f, -0.923879533f};
    const float S16[8] = {0.0f, 0.382683432f, 0.707106781f, 0.923879533f,
                          1.0f, 0.923879533f, 0.707106781f, 0.382683432f};
#pragma unroll
    for (int j = 0; j < 8; j++) {
        float2 u = r[j], v = r[j + 8];
        float2 d = csub(u, v);
        r[j] = cadd(u, v);
        r[j + 8] = (j == 0) ? d : cmul(d, make_float2(C16[j], sg * S16[j]));
    }
    const float C8[4] = {1.0f, 0.707106781f, 0.0f, -0.707106781f};
    const float S8[4] = {0.0f, 0.707106781f, 1.0f, 0.707106781f};
#pragma unroll
    for (int b = 0; b < 16; b += 8) {
#pragma unroll
        for (int j = 0; j < 4; j++) {
            float2 u = r[b + j], v = r[b + j + 4];
            float2 d = csub(u, v);
            r[b + j] = cadd(u, v);
            r[b + j + 4] = (j == 0) ? d : cmul(d, make_float2(C8[j], sg * S8[j]));
        }
    }
#pragma unroll
    for (int b = 0; b < 16; b += 4) {
        // j = 0: tw = 1
        {
            float2 u = r[b], v = r[b + 2];
            r[b] = cadd(u, v);
            r[b + 2] = csub(u, v);
        }
        // j = 1: tw = (0, sg) -> (x,y) * (0,sg) = (-sg*y, sg*x)
        {
            float2 u = r[b + 1], v = r[b + 3];
            float2 d = csub(u, v);
            r[b + 1] = cadd(u, v);
            r[b + 3] = make_float2(-sg * d.y, sg * d.x);
        }
    }
#pragma unroll
    for (int b = 0; b < 16; b += 2) {
        float2 u = r[b], v = r[b + 1];
        r[b] = cadd(u, v);
        r[b + 1] = csub(u, v);
    }
}

// shared-memory layouts for 16 independent 256-pt pipelines per block
#define NAT(i, g)      ((i) * 17 + (g))                  // natural order,    max 4350
#define PADX(k1, t, g) ((g) * 272 + (k1) * 17 + (t))     // transposed order, max 4350
#define BUFSZ 4352

// core: buf holds u[i] = x_shift[i]*c1[i] in NAT layout. Produces y = ifft(fft(u)*c2)
// (including the 1/256? NO: 1/256 is folded into g_scale by caller) in registers:
// rout[j] = y[m], m = t + 16*brev4(j).
static __device__ __forceinline__ void frft_core(float2* buf, const float2* sc2,
                                                 const float2* sw, int t, int g,
                                                 float2* rout) {
    const int BR[16] = {0, 8, 4, 12, 2, 10, 6, 14, 1, 9, 5, 13, 3, 11, 7, 15};
    float2 r[16];

    // ---- forward FFT, step 1: DFT-16 over n1 (stride-16 gather), twiddle W256^(t*k1)
#pragma unroll
    for (int n1 = 0; n1 < 16; n1++) r[n1] = buf[NAT(16 * n1 + t, g)];
    __syncthreads();
    fft16<-1>(r);
#pragma unroll
    for (int j = 0; j < 16; j++) {
        int k1 = BR[j];
        float2 v = r[j];
        int m = (t * k1) & 255;
        if (m) v = cmul(v, sw[m]);
        buf[PADX(k1, t, g)] = v;
    }
    __syncthreads();

    // ---- forward FFT, step 2: DFT-16 over n2; k = t + 16*brev4(j); multiply c2; store natural
#pragma unroll
    for (int n2 = 0; n2 < 16; n2++) r[n2] = buf[PADX(t, n2, g)];
    __syncthreads();
    fft16<-1>(r);
#pragma unroll
    for (int j = 0; j < 16; j++) {
        int k = t + 16 * BR[j];
        buf[NAT(k, g)] = cmul(r[j], sc2[k]);
    }
    __syncthreads();

    // ---- inverse FFT, step 1
#pragma unroll
    for (int n1 = 0; n1 < 16; n1++) r[n1] = buf[NAT(16 * n1 + t, g)];
    __syncthreads();
    fft16<1>(r);
#pragma unroll
    for (int j = 0; j < 16; j++) {
        int k1 = BR[j];
        float2 v = r[j];
        int m = (t * k1) & 255;
        if (m) {
            float2 wv = sw[m];
            v = cmul(v, make_float2(wv.x, -wv.y));  // conj -> e^{+2pi i t k1/256}
        }
        buf[PADX(k1, t, g)] = v;
    }
    __syncthreads();

    // ---- inverse FFT, step 2
#pragma unroll
    for (int n2 = 0; n2 < 16; n2++) r[n2] = buf[PADX(t, n2, g)];
    __syncthreads();  // all reads done; caller may rewrite buf
    fft16<1>(r);
#pragma unroll
    for (int j = 0; j < 16; j++) rout[j] = r[j];
}

// ---------- kernel 0: build chirp / twiddle tables from alpha ----------
__global__ void k_init(const float* __restrict__ alpha) {
    int i = threadIdx.x;  // 256 threads
    float a = fminf(fmaxf(alpha[0], 1e-4f), 2.0f - 1e-4f);
    float s4, c4;
    sincospif(a * 0.25f, &s4, &c4);
    float tan_a2 = s4 / c4;                 // tan(a*pi/4)
    float sin_a = sinpif(a * 0.5f);         // sin(a*pi/2)
    float n = (float)(i - 128);
    float n2 = n * n;
    float s, c;
    sincospif(-n2 * tan_a2 * (1.0f / 256.0f), &s, &c);
    g_c1[i] = make_float2(c, s);
    sincospif(-n2 / (256.0f * sin_a), &s, &c);
    g_c2[i] = make_float2(c, s);
    sincospif(-(float)i * (2.0f / 256.0f), &s, &c);
    g_w256[i] = make_float2(c, s);
    if (i == 0) g_scale = 1.0f / (256.0f * sqrtf(fabsf(sin_a) + 1e-12f));
}

// ---------- kernel 1: FRFT along W (rows). 16 rows/block. ----------
__global__ void __launch_bounds__(256) k_frft_w(const float* __restrict__ x) {
    __shared__ float2 buf[BUFSZ];
    __shared__ float2 sc1[256], sc2[256], sw[256];
    float2* scr = reinterpret_cast<float2*>(g_scratch4);

    int tid = threadIdx.x;
    sc1[tid] = g_c1[tid];
    sc2[tid] = g_c2[tid];
    sw[tid] = g_w256[tid];
    __syncthreads();

    int rowbase0 = blockIdx.x * 16 * 256;
    float2 c1t = sc1[tid];
    int src_col = (tid + 128) & 255;  // ifftshift
#pragma unroll
    for (int k = 0; k < 16; k++) {
        float xv = x[rowbase0 + k * 256 + src_col];
        buf[NAT(tid, k)] = make_float2(xv * c1t.x, xv * c1t.y);
    }
    __syncthreads();

    int t = tid & 15, g = tid >> 4;
    float2 r[16];
    frft_core(buf, sc2, sw, t, g, r);

    float scale = g_scale;
    int base = rowbase0 + g * 256;
    const int BR[16] = {0, 8, 4, 12, 2, 10, 6, 14, 1, 9, 5, 13, 3, 11, 7, 15};
#pragma unroll
    for (int j = 0; j < 16; j++) {
        int m = t + 16 * BR[j];
        float2 v = cmul(r[j], sc1[m]);
        v.x *= scale;
        v.y *= scale;
        scr[base + ((m + 128) & 255)] = v;  // fftshift on store
    }
}

// ---------- kernel 2: FRFT along H (columns), in place, tiled for coalescing ----------
__global__ void __launch_bounds__(256) k_frft_h() {
    __shared__ float2 buf[BUFSZ];
    __shared__ float2 sc1[256], sc2[256], sw[256];
    float2* scr = reinterpret_cast<float2*>(g_scratch4);

    int tid = threadIdx.x;
    sc1[tid] = g_c1[tid];
    sc2[tid] = g_c2[tid];
    sw[tid] = g_w256[tid];
    __syncthreads();

    int plane = blockIdx.x >> 4;          // 0..127  (b*C + c)
    int w0 = (blockIdx.x & 15) * 16;      // column tile
    int pbase = plane * PLANE;

    // load 256(h) x 16(w) tile, ifftshift along h, multiply c1[h]
#pragma unroll
    for (int k = 0; k < 16; k++) {
        int e = tid + 256 * k;
        int h = e >> 4;
        int wq = e & 15;
        float2 v = scr[pbase + ((h + 128) & 255) * 256 + w0 + wq];
        buf[NAT(h, wq)] = cmul(v, sc1[h]);
    }
    __syncthreads();

    int t = tid & 15, g = tid >> 4;  // g = column within tile
    float2 r[16];
    frft_core(buf, sc2, sw, t, g, r);
    __syncthreads();  // safe to rewrite buf

    float scale = g_scale;
    const int BR[16] = {0, 8, 4, 12, 2, 10, 6, 14, 1, 9, 5, 13, 3, 11, 7, 15};
#pragma unroll
    for (int j = 0; j < 16; j++) {
        int m = t + 16 * BR[j];
        float2 v = cmul(r[j], sc1[m]);
        v.x *= scale;
        v.y *= scale;
        buf[NAT((m + 128) & 255, g)] = v;  // fftshift into shared
    }
    __syncthreads();

    // coalesced global write-back (in place)
#pragma unroll
    for (int k = 0; k < 16; k++) {
        int e = tid + 256 * k;
        int o = e >> 4;
        int wq = e & 15;
        scr[pbase + o * 256 + w0 + wq] = buf[NAT(o, wq)];
    }
}

// ---------- kernel 3: mag/phase + 1x1 conv (general w). 2 pixels/thread. ----------
__global__ void __launch_bounds__(256) k_conv(const float* __restrict__ w,
                                              float* __restrict__ out) {
    __shared__ float ws[CHN * 2 * CHN];  // 2048
    const float2* Y = reinterpret_cast<const float2*>(g_scratch4);

    int tid = threadIdx.x;
#pragma unroll
    for (int i = tid; i < 2048; i += 256) ws[i] = w[i];
    __syncthreads();

    int gid = blockIdx.x * 256 + tid;  // 0..131071
    int p = gid << 1;                  // first of 2 pixels
    int b = p >> 16;
    int hw = p & 65535;
    const float2* base = Y + b * (CHN * PLANE) + hw;

    float acc0[CHN], acc1[CHN];
#pragma unroll
    for (int o = 0; o < CHN; o++) {
        acc0[o] = 0.0f;
        acc1[o] = 0.0f;
    }

    const float INV_PI = 0.318309886f;
#pragma unroll 2
    for (int c = 0; c < CHN; c++) {
        float4 z = *reinterpret_cast<const float4*>(base + c * PLANE);  // 2 complex
        float m0 = sqrtf(fmaf(z.x, z.x, z.y * z.y));
        float p0 = atan2f(z.y, z.x) * INV_PI;
        float m1 = sqrtf(fmaf(z.z, z.z, z.w * z.w));
        float p1 = atan2f(z.w, z.z) * INV_PI;
#pragma unroll
        for (int o = 0; o < CHN; o++) {
            float wm = ws[o * 64 + c];
            float wp = ws[o * 64 + 32 + c];
            acc0[o] = fmaf(wm, m0, fmaf(wp, p0, acc0[o]));
            acc1[o] = fmaf(wm, m1, fmaf(wp, p1, acc1[o]));
        }
    }

    float* ob = out + b * (CHN * PLANE) + hw;
#pragma unroll
    for (int o = 0; o < CHN; o++) {
        *reinterpret_cast<float2*>(ob + o * PLANE) = make_float2(acc0[o], acc1[o]);
    }
}

// ---------- launcher ----------
extern "C" void kernel_launch(void* const* d_in, const int* in_sizes, int n_in,
                              void* d_out, int out_size) {
    // identify inputs by element count (x: 8388608, alpha: 1, w: 2048)
    const float* x = nullptr;
    const float* alpha = nullptr;
    const float* w = nullptr;
    for (int i = 0; i < n_in; i++) {
        if (in_sizes[i] == 1)
            alpha = (const float*)d_in[i];
        else if (in_sizes[i] == CHN * 2 * CHN)
            w = (const float*)d_in[i];
        else
            x = (const float*)d_in[i];
    }
    float* out = (float*)d_out;

    k_init<<<1, 256>>>(alpha);
    k_frft_w<<<NROWS / 16, 256>>>(x);
    k_frft_h<<<(BATCH * CHN * WDIM) / 16, 256>>>();
    k_conv<<<NPIX / 2 / 256, 256>>>(w, out);
}

// round 6
// speedup vs baseline: 1.0106x; 1.0106x over previous
#include <cuda_runtime.h>
#include <math.h>

// Shapes (fixed by the problem)
#define BATCH 4
#define CHN   32
#define HDIM  256
#define WDIM  256
#define PLANE (HDIM * WDIM)           // 65536
#define NPIX  (BATCH * PLANE)         // 262144
#define NROWS (BATCH * CHN * HDIM)    // 32768 rows (W pass)
#define NEL   (BATCH * CHN * PLANE)   // 8388608 complex elements

// ---------- global scratch / tables (static device memory only) ----------
__device__ float4 g_scratch4[NEL / 2];          // 8388608 float2 viewed as float4 (16B aligned)
__device__ float2 g_c1[256];
__device__ float2 g_c2[256];
__device__ float2 g_w256[256];                  // exp(-2*pi*i*m/256)
__device__ float  g_scale;

// ---------- complex helpers ----------
static __device__ __forceinline__ float2 cmul(float2 a, float2 b) {
    return make_float2(fmaf(a.x, b.x, -(a.y * b.y)), fmaf(a.x, b.y, a.y * b.x));
}
static __device__ __forceinline__ float2 cadd(float2 a, float2 b) {
    return make_float2(a.x + b.x, a.y + b.y);
}
static __device__ __forceinline__ float2 csub(float2 a, float2 b) {
    return make_float2(a.x - b.x, a.y - b.y);
}

// ---------- packed f32x2 helpers (Blackwell FFMA2 via PTX; ptxas never auto-fuses) ----
static __device__ __forceinline__ unsigned long long pack2(float a, float b) {
    unsigned long long r;
    asm("mov.b64 %0, {%1, %2};" : "=l"(r) : "f"(a), "f"(b));
    return r;
}
static __device__ __forceinline__ void fma2(unsigned long long& d,
                                            unsigned long long a,
                                            unsigned long long b) {
    asm("fma.rn.f32x2 %0, %1, %2, %0;" : "+l"(d) : "l"(a), "l"(b));
}
static __device__ __forceinline__ void unpack2(unsigned long long v, float& a, float& b) {
    asm("mov.b64 {%0, %1}, %2;" : "=f"(a), "=f"(b) : "l"(v));
}

// ---------- register DFT-16: DIF radix-2, natural in, bit-reversed out ----------
template <int S>
static __device__ __forceinline__ void fft16(float2* r) {
    const float sg = (float)S;
    const float C16[8] = {1.0f, 0.923879533f, 0.707106781f, 0.382683432f,
                          0.0f, -0.382683432f, -0.707106781f, -0.923879533f};
    const float S16[8] = {0.0f, 0.382683432f, 0.707106781f, 0.923879533f,
                          1.0f, 0.923879533f, 0.707106781f, 0.382683432f};
#pragma unroll
    for (int j = 0; j < 8; j++) {
        float2 u = r[j], v = r[j + 8];
        float2 d = csub(u, v);
        r[j] = cadd(u, v);
        r[j + 8] = (j == 0) ? d : cmul(d, make_float2(C16[j], sg * S16[j]));
    }
    const float C8[4] = {1.0f, 0.707106781f, 0.0f, -0.707106781f};
    const float S8[4] = {0.0f, 0.707106781f, 1.0f, 0.707106781f};
#pragma unroll
    for (int b = 0; b < 16; b += 8) {
#pragma unroll
        for (int j = 0; j < 4; j++) {
            float2 u = r[b + j], v = r[b + j + 4];
            float2 d = csub(u, v);
            r[b + j] = cadd(u, v);
            r[b + j + 4] = (j == 0) ? d : cmul(d, make_float2(C8[j], sg * S8[j]));
        }
    }
#pragma unroll
    for (int b = 0; b < 16; b += 4) {
        {
            float2 u = r[b], v = r[b + 2];
            r[b] = cadd(u, v);
            r[b + 2] = csub(u, v);
        }
        {
            float2 u = r[b + 1], v = r[b + 3];
            float2 d = csub(u, v);
            r[b + 1] = cadd(u, v);
            r[b + 3] = make_float2(-sg * d.y, sg * d.x);
        }
    }
#pragma unroll
    for (int b = 0; b < 16; b += 2) {
        float2 u = r[b], v = r[b + 1];
        r[b] = cadd(u, v);
        r[b + 1] = csub(u, v);
    }
}

// shared-memory layouts for 16 independent 256-pt pipelines per block
#define NAT(i, g)      ((i) * 17 + (g))                  // natural order,    max 4350
#define PADX(k1, t, g) ((g) * 272 + (k1) * 17 + (t))     // transposed order, max 4350
#define BUFSZ 4352

// core: buf holds u[i] = x_shift[i]*c1[i] in NAT layout. Produces y = ifft(fft(u)*c2)
// (1/256 folded into g_scale by caller) in registers: rout[j] = y[m], m = t + 16*brev4(j).
// On return, all shared reads are complete (sync precedes the final register fft16),
// so callers may immediately rewrite buf.
static __device__ __forceinline__ void frft_core(float2* buf, const float2* sc2,
                                                 const float2* sw, int t, int g,
                                                 float2* rout) {
    const int BR[16] = {0, 8, 4, 12, 2, 10, 6, 14, 1, 9, 5, 13, 3, 11, 7, 15};
    float2 r[16];

    // ---- forward FFT, step 1
#pragma unroll
    for (int n1 = 0; n1 < 16; n1++) r[n1] = buf[NAT(16 * n1 + t, g)];
    __syncthreads();
    fft16<-1>(r);
#pragma unroll
    for (int j = 0; j < 16; j++) {
        int k1 = BR[j];
        float2 v = r[j];
        int m = (t * k1) & 255;
        if (m) v = cmul(v, sw[m]);
        buf[PADX(k1, t, g)] = v;
    }
    __syncthreads();

    // ---- forward FFT, step 2 + kernel chirp c2
#pragma unroll
    for (int n2 = 0; n2 < 16; n2++) r[n2] = buf[PADX(t, n2, g)];
    __syncthreads();
    fft16<-1>(r);
#pragma unroll
    for (int j = 0; j < 16; j++) {
        int k = t + 16 * BR[j];
        buf[NAT(k, g)] = cmul(r[j], sc2[k]);
    }
    __syncthreads();

    // ---- inverse FFT, step 1
#pragma unroll
    for (int n1 = 0; n1 < 16; n1++) r[n1] = buf[NAT(16 * n1 + t, g)];
    __syncthreads();
    fft16<1>(r);
#pragma unroll
    for (int j = 0; j < 16; j++) {
        int k1 = BR[j];
        float2 v = r[j];
        int m = (t * k1) & 255;
        if (m) {
            float2 wv = sw[m];
            v = cmul(v, make_float2(wv.x, -wv.y));
        }
        buf[PADX(k1, t, g)] = v;
    }
    __syncthreads();

    // ---- inverse FFT, step 2
#pragma unroll
    for (int n2 = 0; n2 < 16; n2++) r[n2] = buf[PADX(t, n2, g)];
    __syncthreads();
    fft16<1>(r);
#pragma unroll
    for (int j = 0; j < 16; j++) rout[j] = r[j];
}

// ---------- kernel 0: build chirp / twiddle tables from alpha ----------
__global__ void k_init(const float* __restrict__ alpha) {
    int i = threadIdx.x;  // 256 threads
    float a = fminf(fmaxf(alpha[0], 1e-4f), 2.0f - 1e-4f);
    float s4, c4;
    sincospif(a * 0.25f, &s4, &c4);
    float tan_a2 = s4 / c4;                 // tan(a*pi/4)
    float sin_a = sinpif(a * 0.5f);         // sin(a*pi/2)
    float n = (float)(i - 128);
    float n2 = n * n;
    float s, c;
    sincospif(-n2 * tan_a2 * (1.0f / 256.0f), &s, &c);
    g_c1[i] = make_float2(c, s);
    sincospif(-n2 / (256.0f * sin_a), &s, &c);
    g_c2[i] = make_float2(c, s);
    sincospif(-(float)i * (2.0f / 256.0f), &s, &c);
    g_w256[i] = make_float2(c, s);
    if (i == 0) g_scale = 1.0f / (256.0f * sqrtf(fabsf(sin_a) + 1e-12f));
}

// ---------- kernel 1: FRFT along W (rows). 16 rows/block, coalesced in AND out. ----------
__global__ void __launch_bounds__(256) k_frft_w(const float* __restrict__ x) {
    __shared__ float2 buf[BUFSZ];
    __shared__ float2 sc1[256], sc2[256], sw[256];
    float2* scr = reinterpret_cast<float2*>(g_scratch4);

    int tid = threadIdx.x;
    sc1[tid] = g_c1[tid];
    sc2[tid] = g_c2[tid];
    sw[tid] = g_w256[tid];
    __syncthreads();

    int rowbase0 = blockIdx.x * 16 * 256;
    float2 c1t = sc1[tid];
    int src_col = (tid + 128) & 255;  // ifftshift
#pragma unroll
    for (int k = 0; k < 16; k++) {
        float xv = x[rowbase0 + k * 256 + src_col];
        buf[NAT(tid, k)] = make_float2(xv * c1t.x, xv * c1t.y);
    }
    __syncthreads();

    int t = tid & 15, g = tid >> 4;
    float2 r[16];
    frft_core(buf, sc2, sw, t, g, r);

    float scale = g_scale;
    const int BR[16] = {0, 8, 4, 12, 2, 10, 6, 14, 1, 9, 5, 13, 3, 11, 7, 15};
    // stage fftshifted result into shared, then write coalesced rows
    // (direct scatter had stride-16 stores: 1 useful 8B per 128B line at L2)
#pragma unroll
    for (int j = 0; j < 16; j++) {
        int m = t + 16 * BR[j];
        float2 v = cmul(r[j], sc1[m]);
        v.x *= scale;
        v.y *= scale;
        buf[NAT((m + 128) & 255, g)] = v;  // fftshift into shared
    }
    __syncthreads();
#pragma unroll
    for (int k = 0; k < 16; k++) {
        scr[rowbase0 + k * 256 + tid] = buf[NAT(tid, k)];
    }
}

// ---------- kernel 2: FRFT along H (columns), in place, tiled for coalescing ----------
__global__ void __launch_bounds__(256) k_frft_h() {
    __shared__ float2 buf[BUFSZ];
    __shared__ float2 sc1[256], sc2[256], sw[256];
    float2* scr = reinterpret_cast<float2*>(g_scratch4);

    int tid = threadIdx.x;
    sc1[tid] = g_c1[tid];
    sc2[tid] = g_c2[tid];
    sw[tid] = g_w256[tid];
    __syncthreads();

    int plane = blockIdx.x >> 4;          // 0..127  (b*C + c)
    int w0 = (blockIdx.x & 15) * 16;      // column tile
    int pbase = plane * PLANE;

    // load 256(h) x 16(w) tile, ifftshift along h, multiply c1[h]
#pragma unroll
    for (int k = 0; k < 16; k++) {
        int e = tid + 256 * k;
        int h = e >> 4;
        int wq = e & 15;
        float2 v = scr[pbase + ((h + 128) & 255) * 256 + w0 + wq];
        buf[NAT(h, wq)] = cmul(v, sc1[h]);
    }
    __syncthreads();

    int t = tid & 15, g = tid >> 4;  // g = column within tile
    float2 r[16];
    frft_core(buf, sc2, sw, t, g, r);

    float scale = g_scale;
    const int BR[16] = {0, 8, 4, 12, 2, 10, 6, 14, 1, 9, 5, 13, 3, 11, 7, 15};
#pragma unroll
    for (int j = 0; j < 16; j++) {
        int m = t + 16 * BR[j];
        float2 v = cmul(r[j], sc1[m]);
        v.x *= scale;
        v.y *= scale;
        buf[NAT((m + 128) & 255, g)] = v;  // fftshift into shared
    }
    __syncthreads();

    // coalesced global write-back (in place)
#pragma unroll
    for (int k = 0; k < 16; k++) {
        int e = tid + 256 * k;
        int o = e >> 4;
        int wq = e & 15;
        scr[pbase + o * 256 + w0 + wq] = buf[NAT(o, wq)];
    }
}

// ---------- kernel 3: mag/phase + 1x1 conv, f32x2-packed. 2 pixels/thread. ----------
// Weights pre-duplicated in shared as {wm,wm, wp/pi,wp/pi} per (o,c):
// one broadcast LDS.128 feeds 2 FFMA2 (8 scalar FMA lanes).
__global__ void __launch_bounds__(256) k_conv(const float* __restrict__ w,
                                              float* __restrict__ out) {
    __shared__ ulonglong2 ws2[CHN * CHN];  // [o][c] = {pack2(wm,wm), pack2(wp/pi,wp/pi)} — 16KB
    const float2* Y = reinterpret_cast<const float2*>(g_scratch4);

    const float INV_PI = 0.318309886f;
    int tid = threadIdx.x;
#pragma unroll
    for (int i = tid; i < CHN * CHN; i += 256) {
        int o = i >> 5, c = i & 31;
        float wm = w[o * 64 + c];
        float wp = w[o * 64 + 32 + c] * INV_PI;   // fold 1/pi into the phase weight
        ulonglong2 v;
        v.x = pack2(wm, wm);
        v.y = pack2(wp, wp);
        ws2[i] = v;
    }
    __syncthreads();

    int gid = blockIdx.x * 256 + tid;  // 0..131071
    int p = gid << 1;                  // first of 2 pixels
    int b = p >> 16;
    int hw = p & 65535;
    const float2* base = Y + b * (CHN * PLANE) + hw;

    unsigned long long acc[CHN];
#pragma unroll
    for (int o = 0; o < CHN; o++) acc[o] = 0ULL;  // bits of (0.f, 0.f)

#pragma unroll 4
    for (int c = 0; c < CHN; c++) {
        float4 z = *reinterpret_cast<const float4*>(base + c * PLANE);  // 2 complex
        float m0 = sqrtf(fmaf(z.x, z.x, z.y * z.y));
        float p0 = atan2f(z.y, z.x);
        float m1 = sqrtf(fmaf(z.z, z.z, z.w * z.w));
        float p1 = atan2f(z.w, z.z);
        unsigned long long mp = pack2(m0, m1);
        unsigned long long pp = pack2(p0, p1);
        const ulonglong2* wrow = ws2 + c;
#pragma unroll
        for (int o = 0; o < CHN; o++) {
            ulonglong2 wv = wrow[o * CHN];   // broadcast LDS.128
            fma2(acc[o], wv.x, mp);
            fma2(acc[o], wv.y, pp);
        }
    }

    float* ob = out + b * (CHN * PLANE) + hw;
#pragma unroll
    for (int o = 0; o < CHN; o++) {
        float a0, a1;
        unpack2(acc[o], a0, a1);
        *reinterpret_cast<float2*>(ob + o * PLANE) = make_float2(a0, a1);
    }
}

// ---------- launcher ----------
extern "C" void kernel_launch(void* const* d_in, const int* in_sizes, int n_in,
                              void* d_out, int out_size) {
    const float* x = nullptr;
    const float* alpha = nullptr;
    const float* w = nullptr;
    for (int i = 0; i < n_in; i++) {
        if (in_sizes[i] == 1)
            alpha = (const float*)d_in[i];
        else if (in_sizes[i] == CHN * 2 * CHN)
            w = (const float*)d_in[i];
        else
            x = (const float*)d_in[i];
    }
    float* out = (float*)d_out;

    k_init<<<1, 256>>>(alpha);
    k_frft_w<<<NROWS / 16, 256>>>(x);
    k_frft_h<<<(BATCH * CHN * WDIM) / 16, 256>>>();
    k_conv<<<NPIX / 2 / 256, 256>>>(w, out);
}

// round 7
// speedup vs baseline: 1.0126x; 1.0020x over previous
#include <cuda_runtime.h>
#include <math.h>

// Shapes (fixed by the problem)
#define BATCH 4
#define CHN   32
#define HDIM  256
#define WDIM  256
#define PLANE (HDIM * WDIM)           // 65536
#define NPIX  (BATCH * PLANE)         // 262144
#define NROWS (BATCH * CHN * HDIM)    // 32768 rows (W pass)
#define NEL   (BATCH * CHN * PLANE)   // 8388608 complex elements

// ---------- global scratch / tables (static device memory only) ----------
__device__ float4 g_scratch4[NEL / 2];          // 8388608 float2 viewed as float4 (16B aligned)
__device__ float2 g_c1[256];
__device__ float2 g_c2[256];
__device__ float2 g_w256[256];                  // exp(-2*pi*i*m/256)
__device__ float  g_scale;

// ---------- complex helpers ----------
static __device__ __forceinline__ float2 cmul(float2 a, float2 b) {
    return make_float2(fmaf(a.x, b.x, -(a.y * b.y)), fmaf(a.x, b.y, a.y * b.x));
}
static __device__ __forceinline__ float2 cadd(float2 a, float2 b) {
    return make_float2(a.x + b.x, a.y + b.y);
}
static __device__ __forceinline__ float2 csub(float2 a, float2 b) {
    return make_float2(a.x - b.x, a.y - b.y);
}

// ---------- packed f32x2 helpers (Blackwell FFMA2 via PTX; ptxas never auto-fuses) ----
static __device__ __forceinline__ unsigned long long pack2(float a, float b) {
    unsigned long long r;
    asm("mov.b64 %0, {%1, %2};" : "=l"(r) : "f"(a), "f"(b));
    return r;
}
static __device__ __forceinline__ void fma2(unsigned long long& d,
                                            unsigned long long a,
                                            unsigned long long b) {
    asm("fma.rn.f32x2 %0, %1, %2, %0;" : "+l"(d) : "l"(a), "l"(b));
}
static __device__ __forceinline__ void unpack2(unsigned long long v, float& a, float& b) {
    asm("mov.b64 {%0, %1}, %2;" : "=f"(a), "=f"(b) : "l"(v));
}

// ---------- register DFT-16: DIF radix-2, natural in, bit-reversed out ----------
template <int S>
static __device__ __forceinline__ void fft16(float2* r) {
    const float sg = (float)S;
    const float C16[8] = {1.0f, 0.923879533f, 0.707106781f, 0.382683432f,
                          0.0f, -0.382683432f, -0.707106781f, -0.923879533f};
    const float S16[8] = {0.0f, 0.382683432f, 0.707106781f, 0.923879533f,
                          1.0f, 0.923879533f, 0.707106781f, 0.382683432f};
#pragma unroll
    for (int j = 0; j < 8; j++) {
        float2 u = r[j], v = r[j + 8];
        float2 d = csub(u, v);
        r[j] = cadd(u, v);
        r[j + 8] = (j == 0) ? d : cmul(d, make_float2(C16[j], sg * S16[j]));
    }
    const float C8[4] = {1.0f, 0.707106781f, 0.0f, -0.707106781f};
    const float S8[4] = {0.0f, 0.707106781f, 1.0f, 0.707106781f};
#pragma unroll
    for (int b = 0; b < 16; b += 8) {
#pragma unroll
        for (int j = 0; j < 4; j++) {
            float2 u = r[b + j], v = r[b + j + 4];
            float2 d = csub(u, v);
            r[b + j] = cadd(u, v);
            r[b + j + 4] = (j == 0) ? d : cmul(d, make_float2(C8[j], sg * S8[j]));
        }
    }
#pragma unroll
    for (int b = 0; b < 16; b += 4) {
        {
            float2 u = r[b], v = r[b + 2];
            r[b] = cadd(u, v);
            r[b + 2] = csub(u, v);
        }
        {
            float2 u = r[b + 1], v = r[b + 3];
            float2 d = csub(u, v);
            r[b + 1] = cadd(u, v);
            r[b + 3] = make_float2(-sg * d.y, sg * d.x);
        }
    }
#pragma unroll
    for (int b = 0; b < 16; b += 2) {
        float2 u = r[b], v = r[b + 1];
        r[b] = cadd(u, v);
        r[b + 1] = csub(u, v);
    }
}

// shared-memory layouts for 16 independent 256-pt pipelines per block
#define NAT(i, g)      ((i) * 17 + (g))                  // natural order,    max 4350
#define PADX(k1, t, g) ((g) * 272 + (k1) * 17 + (t))     // transposed order, max 4350
#define BUFSZ 4352

// core: buf holds u[i] = x_shift[i]*c1[i] in NAT layout. Produces y = ifft(fft(u)*c2)
// (1/256 folded into g_scale by caller) in registers: rout[j] = y[m], m = t + 16*brev4(j).
// On return, all shared reads are complete (sync precedes the final register fft16),
// so callers may immediately rewrite buf.
static __device__ __forceinline__ void frft_core(float2* buf, const float2* sc2,
                                                 const float2* sw, int t, int g,
                                                 float2* rout) {
    const int BR[16] = {0, 8, 4, 12, 2, 10, 6, 14, 1, 9, 5, 13, 3, 11, 7, 15};
    float2 r[16];

    // ---- forward FFT, step 1
#pragma unroll
    for (int n1 = 0; n1 < 16; n1++) r[n1] = buf[NAT(16 * n1 + t, g)];
    __syncthreads();
    fft16<-1>(r);
#pragma unroll
    for (int j = 0; j < 16; j++) {
        int k1 = BR[j];
        float2 v = r[j];
        int m = (t * k1) & 255;
        if (m) v = cmul(v, sw[m]);
        buf[PADX(k1, t, g)] = v;
    }
    __syncthreads();

    // ---- forward FFT, step 2 + kernel chirp c2
#pragma unroll
    for (int n2 = 0; n2 < 16; n2++) r[n2] = buf[PADX(t, n2, g)];
    __syncthreads();
    fft16<-1>(r);
#pragma unroll
    for (int j = 0; j < 16; j++) {
        int k = t + 16 * BR[j];
        buf[NAT(k, g)] = cmul(r[j], sc2[k]);
    }
    __syncthreads();

    // ---- inverse FFT, step 1
#pragma unroll
    for (int n1 = 0; n1 < 16; n1++) r[n1] = buf[NAT(16 * n1 + t, g)];
    __syncthreads();
    fft16<1>(r);
#pragma unroll
    for (int j = 0; j < 16; j++) {
        int k1 = BR[j];
        float2 v = r[j];
        int m = (t * k1) & 255;
        if (m) {
            float2 wv = sw[m];
            v = cmul(v, make_float2(wv.x, -wv.y));
        }
        buf[PADX(k1, t, g)] = v;
    }
    __syncthreads();

    // ---- inverse FFT, step 2
#pragma unroll
    for (int n2 = 0; n2 < 16; n2++) r[n2] = buf[PADX(t, n2, g)];
    __syncthreads();
    fft16<1>(r);
#pragma unroll
    for (int j = 0; j < 16; j++) rout[j] = r[j];
}

// ---------- kernel 0: build chirp / twiddle tables from alpha ----------
__global__ void k_init(const float* __restrict__ alpha) {
    int i = threadIdx.x;  // 256 threads
    float a = fminf(fmaxf(alpha[0], 1e-4f), 2.0f - 1e-4f);
    float s4, c4;
    sincospif(a * 0.25f, &s4, &c4);
    float tan_a2 = s4 / c4;                 // tan(a*pi/4)
    float sin_a = sinpif(a * 0.5f);         // sin(a*pi/2)
    float n = (float)(i - 128);
    float n2 = n * n;
    float s, c;
    sincospif(-n2 * tan_a2 * (1.0f / 256.0f), &s, &c);
    g_c1[i] = make_float2(c, s);
    sincospif(-n2 / (256.0f * sin_a), &s, &c);
    g_c2[i] = make_float2(c, s);
    sincospif(-(float)i * (2.0f / 256.0f), &s, &c);
    g_w256[i] = make_float2(c, s);
    if (i == 0) g_scale = 1.0f / (256.0f * sqrtf(fabsf(sin_a) + 1e-12f));
}

// ---------- kernel 1: FRFT along W (rows). 16 rows/block, coalesced in AND out. ----------
__global__ void __launch_bounds__(256) k_frft_w(const float* __restrict__ x) {
    __shared__ float2 buf[BUFSZ];
    __shared__ float2 sc1[256], sc2[256], sw[256];
    float2* scr = reinterpret_cast<float2*>(g_scratch4);

    int tid = threadIdx.x;
    sc1[tid] = g_c1[tid];
    sc2[tid] = g_c2[tid];
    sw[tid] = g_w256[tid];
    __syncthreads();

    int rowbase0 = blockIdx.x * 16 * 256;
    float2 c1t = sc1[tid];
    int src_col = (tid + 128) & 255;  // ifftshift
#pragma unroll
    for (int k = 0; k < 16; k++) {
        float xv = x[rowbase0 + k * 256 + src_col];
        buf[NAT(tid, k)] = make_float2(xv * c1t.x, xv * c1t.y);
    }
    __syncthreads();

    int t = tid & 15, g = tid >> 4;
    float2 r[16];
    frft_core(buf, sc2, sw, t, g, r);

    float scale = g_scale;
    const int BR[16] = {0, 8, 4, 12, 2, 10, 6, 14, 1, 9, 5, 13, 3, 11, 7, 15};
    // stage fftshifted result into shared, then write coalesced rows
    // (direct scatter had stride-16 stores: 1 useful 8B per 128B line at L2)
#pragma unroll
    for (int j = 0; j < 16; j++) {
        int m = t + 16 * BR[j];
        float2 v = cmul(r[j], sc1[m]);
        v.x *= scale;
        v.y *= scale;
        buf[NAT((m + 128) & 255, g)] = v;  // fftshift into shared
    }
    __syncthreads();
#pragma unroll
    for (int k = 0; k < 16; k++) {
        scr[rowbase0 + k * 256 + tid] = buf[NAT(tid, k)];
    }
}

// ---------- kernel 2: FRFT along H (columns), in place, tiled for coalescing ----------
__global__ void __launch_bounds__(256) k_frft_h() {
    __shared__ float2 buf[BUFSZ];
    __shared__ float2 sc1[256], sc2[256], sw[256];
    float2* scr = reinterpret_cast<float2*>(g_scratch4);

    int tid = threadIdx.x;
    sc1[tid] = g_c1[tid];
    sc2[tid] = g_c2[tid];
    sw[tid] = g_w256[tid];
    __syncthreads();

    int plane = blockIdx.x >> 4;          // 0..127  (b*C + c)
    int w0 = (blockIdx.x & 15) * 16;      // column tile
    int pbase = plane * PLANE;

    // load 256(h) x 16(w) tile, ifftshift along h, multiply c1[h]
#pragma unroll
    for (int k = 0; k < 16; k++) {
        int e = tid + 256 * k;
        int h = e >> 4;
        int wq = e & 15;
        float2 v = scr[pbase + ((h + 128) & 255) * 256 + w0 + wq];
        buf[NAT(h, wq)] = cmul(v, sc1[h]);
    }
    __syncthreads();

    int t = tid & 15, g = tid >> 4;  // g = column within tile
    float2 r[16];
    frft_core(buf, sc2, sw, t, g, r);

    float scale = g_scale;
    const int BR[16] = {0, 8, 4, 12, 2, 10, 6, 14, 1, 9, 5, 13, 3, 11, 7, 15};
#pragma unroll
    for (int j = 0; j < 16; j++) {
        int m = t + 16 * BR[j];
        float2 v = cmul(r[j], sc1[m]);
        v.x *= scale;
        v.y *= scale;
        buf[NAT((m + 128) & 255, g)] = v;  // fftshift into shared
    }
    __syncthreads();

    // coalesced global write-back (in place)
#pragma unroll
    for (int k = 0; k < 16; k++) {
        int e = tid + 256 * k;
        int o = e >> 4;
        int wq = e & 15;
        scr[pbase + o * 256 + w0 + wq] = buf[NAT(o, wq)];
    }
}

// ---------- kernel 3: mag/phase + 1x1 conv, f32x2-packed. 2 pixels/thread. ----------
// Weights pre-duplicated in shared as {wm,wm, wp/pi,wp/pi} per (o,c):
// one broadcast LDS.128 feeds 2 FFMA2 (8 scalar FMA lanes).
__global__ void __launch_bounds__(256) k_conv(const float* __restrict__ w,
                                              float* __restrict__ out) {
    __shared__ ulonglong2 ws2[CHN * CHN];  // [o][c] = {pack2(wm,wm), pack2(wp/pi,wp/pi)} — 16KB
    const float2* Y = reinterpret_cast<const float2*>(g_scratch4);

    const float INV_PI = 0.318309886f;
    int tid = threadIdx.x;
#pragma unroll
    for (int i = tid; i < CHN * CHN; i += 256) {
        int o = i >> 5, c = i & 31;
        float wm = w[o * 64 + c];
        float wp = w[o * 64 + 32 + c] * INV_PI;   // fold 1/pi into the phase weight
        ulonglong2 v;
        v.x = pack2(wm, wm);
        v.y = pack2(wp, wp);
        ws2[i] = v;
    }
    __syncthreads();

    int gid = blockIdx.x * 256 + tid;  // 0..131071
    int p = gid << 1;                  // first of 2 pixels
    int b = p >> 16;
    int hw = p & 65535;
    const float2* base = Y + b * (CHN * PLANE) + hw;

    unsigned long long acc[CHN];
#pragma unroll
    for (int o = 0; o < CHN; o++) acc[o] = 0ULL;  // bits of (0.f, 0.f)

#pragma unroll 4
    for (int c = 0; c < CHN; c++) {
        float4 z = *reinterpret_cast<const float4*>(base + c * PLANE);  // 2 complex
        float m0 = sqrtf(fmaf(z.x, z.x, z.y * z.y));
        float p0 = atan2f(z.y, z.x);
        float m1 = sqrtf(fmaf(z.z, z.z, z.w * z.w));
        float p1 = atan2f(z.w, z.z);
        unsigned long long mp = pack2(m0, m1);
        unsigned long long pp = pack2(p0, p1);
        const ulonglong2* wrow = ws2 + c;
#pragma unroll
        for (int o = 0; o < CHN; o++) {
            ulonglong2 wv = wrow[o * CHN];   // broadcast LDS.128
            fma2(acc[o], wv.x, mp);
            fma2(acc[o], wv.y, pp);
        }
    }

    float* ob = out + b * (CHN * PLANE) + hw;
#pragma unroll
    for (int o = 0; o < CHN; o++) {
        float a0, a1;
        unpack2(acc[o], a0, a1);
        *reinterpret_cast<float2*>(ob + o * PLANE) = make_float2(a0, a1);
    }
}

// ---------- launcher ----------
extern "C" void kernel_launch(void* const* d_in, const int* in_sizes, int n_in,
                              void* d_out, int out_size) {
    const float* x = nullptr;
    const float* alpha = nullptr;
    const float* w = nullptr;
    for (int i = 0; i < n_in; i++) {
        if (in_sizes[i] == 1)
            alpha = (const float*)d_in[i];
        else if (in_sizes[i] == CHN * 2 * CHN)
            w = (const float*)d_in[i];
        else
            x = (const float*)d_in[i];
    }
    float* out = (float*)d_out;

    k_init<<<1, 256>>>(alpha);
    k_frft_w<<<NROWS / 16, 256>>>(x);
    k_frft_h<<<(BATCH * CHN * WDIM) / 16, 256>>>();
    k_conv<<<NPIX / 2 / 256, 256>>>(w, out);
}

// round 8
// speedup vs baseline: 1.2683x; 1.2525x over previous
#include <cuda_runtime.h>
#include <math.h>

// Shapes (fixed by the problem)
#define BATCH 4
#define CHN   32
#define HDIM  256
#define WDIM  256
#define PLANE (HDIM * WDIM)           // 65536
#define NPIX  (BATCH * PLANE)         // 262144
#define NROWS (BATCH * CHN * HDIM)    // 32768 rows (W pass)
#define NEL   (BATCH * CHN * PLANE)   // 8388608 complex elements

// ---------- global scratch / tables (static device memory only) ----------
__device__ float4 g_scratch4[NEL / 2];          // 8388608 float2 viewed as float4
__device__ float2 g_c1[256];
__device__ float2 g_c2[256];
__device__ float2 g_w256[256];                  // exp(-2*pi*i*m/256)
__device__ float  g_scale;

// ---------- complex helpers ----------
static __device__ __forceinline__ float2 cmul(float2 a, float2 b) {
    return make_float2(fmaf(a.x, b.x, -(a.y * b.y)), fmaf(a.x, b.y, a.y * b.x));
}
static __device__ __forceinline__ float2 cadd(float2 a, float2 b) {
    return make_float2(a.x + b.x, a.y + b.y);
}
static __device__ __forceinline__ float2 csub(float2 a, float2 b) {
    return make_float2(a.x - b.x, a.y - b.y);
}

// ---------- packed f32x2 helpers (Blackwell FFMA2 via PTX) ----------
static __device__ __forceinline__ unsigned long long pack2(float a, float b) {
    unsigned long long r;
    asm("mov.b64 %0, {%1, %2};" : "=l"(r) : "f"(a), "f"(b));
    return r;
}
static __device__ __forceinline__ void fma2(unsigned long long& d,
                                            unsigned long long a,
                                            unsigned long long b) {
    asm("fma.rn.f32x2 %0, %1, %2, %0;" : "+l"(d) : "l"(a), "l"(b));
}
static __device__ __forceinline__ void unpack2(unsigned long long v, float& a, float& b) {
    asm("mov.b64 {%0, %1}, %2;" : "=f"(a), "=f"(b) : "l"(v));
}

// ---------- register DFT-16: DIF radix-2, natural in, bit-reversed out ----------
template <int S>
static __device__ __forceinline__ void fft16(float2* r) {
    const float sg = (float)S;
    const float C16[8] = {1.0f, 0.923879533f, 0.707106781f, 0.382683432f,
                          0.0f, -0.382683432f, -0.707106781f, -0.923879533f};
    const float S16[8] = {0.0f, 0.382683432f, 0.707106781f, 0.923879533f,
                          1.0f, 0.923879533f, 0.707106781f, 0.382683432f};
#pragma unroll
    for (int j = 0; j < 8; j++) {
        float2 u = r[j], v = r[j + 8];
        float2 d = csub(u, v);
        r[j] = cadd(u, v);
        r[j + 8] = (j == 0) ? d : cmul(d, make_float2(C16[j], sg * S16[j]));
    }
    const float C8[4] = {1.0f, 0.707106781f, 0.0f, -0.707106781f};
    const float S8[4] = {0.0f, 0.707106781f, 1.0f, 0.707106781f};
#pragma unroll
    for (int b = 0; b < 16; b += 8) {
#pragma unroll
        for (int j = 0; j < 4; j++) {
            float2 u = r[b + j], v = r[b + j + 4];
            float2 d = csub(u, v);
            r[b + j] = cadd(u, v);
            r[b + j + 4] = (j == 0) ? d : cmul(d, make_float2(C8[j], sg * S8[j]));
        }
    }
#pragma unroll
    for (int b = 0; b < 16; b += 4) {
        {
            float2 u = r[b], v = r[b + 2];
            r[b] = cadd(u, v);
            r[b + 2] = csub(u, v);
        }
        {
            float2 u = r[b + 1], v = r[b + 3];
            float2 d = csub(u, v);
            r[b + 1] = cadd(u, v);
            r[b + 3] = make_float2(-sg * d.y, sg * d.x);
        }
    }
#pragma unroll
    for (int b = 0; b < 16; b += 2) {
        float2 u = r[b], v = r[b + 1];
        r[b] = cadd(u, v);
        r[b + 1] = csub(u, v);
    }
}

// 8 FFT pipelines per 128-thread block. NAT (staging) and PADX (FFT transpose)
// are SEPARATE buffers so PADX traffic stays warp-private (group g = 16 threads
// with the same tid>>4, contiguous lanes -> one warp holds groups 2w, 2w+1).
#define NAT(i, g)      ((i) * 9 + (g))                   // 256 x 8, pad 9  -> 2304
#define PADX(k1, t, g) ((g) * 272 + (k1) * 17 + (t))     // per-g 272      -> 2176

// core: nat holds u[i] = x_shift[i]*c1[i]. Produces y = ifft(fft(u)*c2) in regs:
// rout[j] = y[m], m = t + 16*brev4(j). Internal syncs are warp-scope only:
// every shared exchange is within one warp's 16-thread group. The c2 multiply
// stays in registers (thread already holds the k = t mod 16 residue class the
// inverse stage-1 needs) -> one shared round trip eliminated.
static __device__ __forceinline__ void frft_core(const float2* nat, float2* pad,
                                                 const float2* sc2, const float2* sw,
                                                 int t, int g, float2* rout) {
    const int BR[16] = {0, 8, 4, 12, 2, 10, 6, 14, 1, 9, 5, 13, 3, 11, 7, 15};
    float2 r[16];

    // ---- forward FFT stage 1 (gather from NAT; caller synced)
#pragma unroll
    for (int n1 = 0; n1 < 16; n1++) r[n1] = nat[NAT(16 * n1 + t, g)];
    fft16<-1>(r);
#pragma unroll
    for (int j = 0; j < 16; j++) {
        int k1 = BR[j];
        float2 v = r[j];
        int m = (t * k1) & 255;
        if (m) v = cmul(v, sw[m]);
        pad[PADX(k1, t, g)] = v;
    }
    __syncwarp();

    // ---- forward FFT stage 2
#pragma unroll
    for (int n2 = 0; n2 < 16; n2++) r[n2] = pad[PADX(t, n2, g)];
    __syncwarp();
    fft16<-1>(r);

    // ---- kernel chirp c2 + register bit-reverse permute (no shared round trip):
    // after stage 2 this thread holds y at k = t + 16*BR[j]; inverse stage 1
    // needs exactly the k = t (mod 16) class ordered by k2 -> r2[BR[j]] = r[j]*c2[k].
    float2 r2[16];
#pragma unroll
    for (int j = 0; j < 16; j++) r2[BR[j]] = cmul(r[j], sc2[t + 16 * BR[j]]);

    // ---- inverse FFT stage 1
    fft16<1>(r2);
#pragma unroll
    for (int j = 0; j < 16; j++) {
        int k1 = BR[j];
        float2 v = r2[j];
        int m = (t * k1) & 255;
        if (m) {
            float2 wv = sw[m];
            v = cmul(v, make_float2(wv.x, -wv.y));
        }
        pad[PADX(k1, t, g)] = v;
    }
    __syncwarp();

    // ---- inverse FFT stage 2
#pragma unroll
    for (int n2 = 0; n2 < 16; n2++) r[n2] = pad[PADX(t, n2, g)];
    fft16<1>(r);
#pragma unroll
    for (int j = 0; j < 16; j++) rout[j] = r[j];
}

// ---------- kernel 0: build chirp / twiddle tables from alpha ----------
__global__ void k_init(const float* __restrict__ alpha) {
    int i = threadIdx.x;  // 256 threads
    float a = fminf(fmaxf(alpha[0], 1e-4f), 2.0f - 1e-4f);
    float s4, c4;
    sincospif(a * 0.25f, &s4, &c4);
    float tan_a2 = s4 / c4;                 // tan(a*pi/4)
    float sin_a = sinpif(a * 0.5f);         // sin(a*pi/2)
    float n = (float)(i - 128);
    float n2 = n * n;
    float s, c;
    sincospif(-n2 * tan_a2 * (1.0f / 256.0f), &s, &c);
    g_c1[i] = make_float2(c, s);
    sincospif(-n2 / (256.0f * sin_a), &s, &c);
    g_c2[i] = make_float2(c, s);
    sincospif(-(float)i * (2.0f / 256.0f), &s, &c);
    g_w256[i] = make_float2(c, s);
    if (i == 0) g_scale = 1.0f / (256.0f * sqrtf(fabsf(sin_a) + 1e-12f));
}

// ---------- kernel 1: FRFT along W (rows). 8 rows/block, 128 threads. ----------
__global__ void __launch_bounds__(128) k_frft_w(const float* __restrict__ x) {
    __shared__ float2 nat[2304];
    __shared__ float2 pad[2176];
    __shared__ float2 sc1[256], sc2[256], sw[256];
    float2* scr = reinterpret_cast<float2*>(g_scratch4);

    int tid = threadIdx.x;
    sc1[tid] = g_c1[tid];           sc1[tid + 128] = g_c1[tid + 128];
    sc2[tid] = g_c2[tid];           sc2[tid + 128] = g_c2[tid + 128];
    sw[tid]  = g_w256[tid];         sw[tid + 128]  = g_w256[tid + 128];

    int rowbase0 = blockIdx.x * 8 * 256;
    // staging in: uses only self-written sc1 entries -> no sync yet
#pragma unroll
    for (int half = 0; half < 2; half++) {
        int i = tid + 128 * half;
        float2 c1i = sc1[i];
        int src = (i + 128) & 255;  // ifftshift
#pragma unroll
        for (int k = 0; k < 8; k++) {
            float xv = x[rowbase0 + k * 256 + src];
            nat[NAT(i, k)] = make_float2(xv * c1i.x, xv * c1i.y);
        }
    }
    __syncthreads();

    int t = tid & 15, g = tid >> 4;
    float2 r[16];
    frft_core(nat, pad, sc2, sw, t, g, r);

    // out-staging: column g of NAT is read/written only by group g (same warp),
    // ordered by program order + core's syncwarps -> no barrier needed here.
    float scale = g_scale;
    const int BR[16] = {0, 8, 4, 12, 2, 10, 6, 14, 1, 9, 5, 13, 3, 11, 7, 15};
#pragma unroll
    for (int j = 0; j < 16; j++) {
        int m = t + 16 * BR[j];
        float2 v = cmul(r[j], sc1[m]);
        nat[NAT((m + 128) & 255, g)] = make_float2(v.x * scale, v.y * scale);  // fftshift
    }
    __syncthreads();
#pragma unroll
    for (int half = 0; half < 2; half++) {
        int i = tid + 128 * half;
#pragma unroll
        for (int k = 0; k < 8; k++)
            scr[rowbase0 + k * 256 + i] = nat[NAT(i, k)];
    }
}

// ---------- kernel 2: FRFT along H (columns), in place, 8-col tiles ----------
__global__ void __launch_bounds__(128) k_frft_h() {
    __shared__ float2 nat[2304];
    __shared__ float2 pad[2176];
    __shared__ float2 sc1[256], sc2[256], sw[256];
    float2* scr = reinterpret_cast<float2*>(g_scratch4);

    int tid = threadIdx.x;
    sc1[tid] = g_c1[tid];           sc1[tid + 128] = g_c1[tid + 128];
    sc2[tid] = g_c2[tid];           sc2[tid + 128] = g_c2[tid + 128];
    sw[tid]  = g_w256[tid];         sw[tid + 128]  = g_w256[tid + 128];
    __syncthreads();  // staging reads sc1[h] cross-thread

    int plane = blockIdx.x >> 5;          // 0..127  (b*C + c)
    int w0 = (blockIdx.x & 31) * 8;       // column tile
    int pbase = plane * PLANE;

    // load 256(h) x 8(w) tile, ifftshift along h, multiply c1[h]
#pragma unroll
    for (int k = 0; k < 16; k++) {
        int e = tid + 128 * k;   // 0..2047
        int h = e >> 3, wq = e & 7;
        float2 v = scr[pbase + ((h + 128) & 255) * 256 + w0 + wq];
        nat[NAT(h, wq)] = cmul(v, sc1[h]);
    }
    __syncthreads();

    int t = tid & 15, g = tid >> 4;  // g = column within tile
    float2 r[16];
    frft_core(nat, pad, sc2, sw, t, g, r);

    float scale = g_scale;
    const int BR[16] = {0, 8, 4, 12, 2, 10, 6, 14, 1, 9, 5, 13, 3, 11, 7, 15};
#pragma unroll
    for (int j = 0; j < 16; j++) {
        int m = t + 16 * BR[j];
        float2 v = cmul(r[j], sc1[m]);
        nat[NAT((m + 128) & 255, g)] = make_float2(v.x * scale, v.y * scale);  // fftshift
    }
    __syncthreads();

    // coalesced global write-back (in place)
#pragma unroll
    for (int k = 0; k < 16; k++) {
        int e = tid + 128 * k;
        int o = e >> 3, wq = e & 7;
        scr[pbase + o * 256 + w0 + wq] = nat[NAT(o, wq)];
    }
}

// ---------- fast helpers for k_conv ----------
static __device__ __forceinline__ float fast_mag(float x, float y) {
    float z2 = fmaf(x, x, y * y);
    float rs;
    asm("rsqrt.approx.f32 %0, %1;" : "=f"(rs) : "f"(z2));
    float m = z2 * rs;
    return (z2 > 0.0f) ? m : 0.0f;
}
static __device__ __forceinline__ float fast_atan2(float y, float x) {
    float ax = fabsf(x), ay = fabsf(y);
    float mx = fmaxf(ax, ay), mn = fminf(ax, ay);
    float rc;
    asm("rcp.approx.f32 %0, %1;" : "=f"(rc) : "f"(mx));
    float t = mn * rc;
    t = (mx == 0.0f) ? 0.0f : t;
    float s = t * t;
    float p = -0.0117212f;
    p = fmaf(p, s, 0.05265332f);
    p = fmaf(p, s, -0.11643287f);
    p = fmaf(p, s, 0.19354346f);
    p = fmaf(p, s, -0.33262347f);
    p = fmaf(p, s, 0.99997726f);
    float r = t * p;
    if (ay > ax) r = 1.57079632679f - r;
    if (x < 0.0f) r = 3.14159265359f - r;
    return copysignf(r, y);
}

// ---------- kernel 3: mag/phase + 1x1 conv. 1 pixel/thread, o-pair f32x2 packing.
// If ALL phase weights are zero (true for the given w: identity on magnitude
// channels), the atan2 + phase-FMA half is skipped entirely — exact math.
__global__ void __launch_bounds__(256, 3) k_conv(const float* __restrict__ w,
                                                 float* __restrict__ out) {
    // [c][op]: packed weight pairs for output channels (2op, 2op+1)
    __shared__ unsigned long long wsm[CHN * 16];  // 4 KB
    __shared__ unsigned long long wsp[CHN * 16];  // 4 KB
    const float2* Y = reinterpret_cast<const float2*>(g_scratch4);

    const float INV_PI = 0.318309886f;
    int tid = threadIdx.x;
    int anyp = 0;
#pragma unroll
    for (int i = tid; i < CHN * 16; i += 256) {
        int c = i >> 4, op = i & 15;
        float wm0 = w[(2 * op) * 64 + c];
        float wm1 = w[(2 * op + 1) * 64 + c];
        float wp0 = w[(2 * op) * 64 + 32 + c] * INV_PI;
        float wp1 = w[(2 * op + 1) * 64 + 32 + c] * INV_PI;
        wsm[i] = pack2(wm0, wm1);
        wsp[i] = pack2(wp0, wp1);
        anyp |= (wp0 != 0.0f) | (wp1 != 0.0f);
    }
    int hasphase = __syncthreads_or(anyp);  // barrier + reduction

    int pix = blockIdx.x * 256 + tid;   // 0..262143
    int b = pix >> 16;
    int hw = pix & 65535;
    const float2* base = Y + b * (CHN * PLANE) + hw;

    unsigned long long acc[16];
#pragma unroll
    for (int op = 0; op < 16; op++) acc[op] = 0ULL;

    if (!hasphase) {
#pragma unroll 4
        for (int c = 0; c < CHN; c++) {
            float2 z = base[c * PLANE];
            float m = fast_mag(z.x, z.y);
            unsigned long long mm = pack2(m, m);
            const ulonglong2* row2 = reinterpret_cast<const ulonglong2*>(wsm + (c << 4));
#pragma unroll
            for (int q = 0; q < 8; q++) {
                ulonglong2 wv = row2[q];   // broadcast LDS.128
                fma2(acc[2 * q], wv.x, mm);
                fma2(acc[2 * q + 1], wv.y, mm);
            }
        }
    } else {
#pragma unroll 2
        for (int c = 0; c < CHN; c++) {
            float2 z = base[c * PLANE];
            float m = fast_mag(z.x, z.y);
            float ph = fast_atan2(z.y, z.x);
            unsigned long long mm = pack2(m, m);
            unsigned long long pp = pack2(ph, ph);
            const ulonglong2* rm = reinterpret_cast<const ulonglong2*>(wsm + (c << 4));
            const ulonglong2* rp = reinterpret_cast<const ulonglong2*>(wsp + (c << 4));
#pragma unroll
            for (int q = 0; q < 8; q++) {
                ulonglong2 wvm = rm[q];
                ulonglong2 wvp = rp[q];
                fma2(acc[2 * q], wvm.x, mm);
                fma2(acc[2 * q + 1], wvm.y, mm);
                fma2(acc[2 * q], wvp.x, pp);
                fma2(acc[2 * q + 1], wvp.y, pp);
            }
        }
    }

    float* ob = out + b * (CHN * PLANE) + hw;
#pragma unroll
    for (int op = 0; op < 16; op++) {
        float a0, a1;
        unpack2(acc[op], a0, a1);
        ob[(2 * op) * PLANE] = a0;
        ob[(2 * op + 1) * PLANE] = a1;
    }
}

// ---------- launcher ----------
extern "C" void kernel_launch(void* const* d_in, const int* in_sizes, int n_in,
                              void* d_out, int out_size) {
    const float* x = nullptr;
    const float* alpha = nullptr;
    const float* w = nullptr;
    for (int i = 0; i < n_in; i++) {
        if (in_sizes[i] == 1)
            alpha = (const float*)d_in[i];
        else if (in_sizes[i] == CHN * 2 * CHN)
            w = (const float*)d_in[i];
        else
            x = (const float*)d_in[i];
    }
    float* out = (float*)d_out;

    k_init<<<1, 256>>>(alpha);
    k_frft_w<<<NROWS / 8, 128>>>(x);
    k_frft_h<<<(BATCH * CHN * WDIM) / 8 , 128>>>();
    k_conv<<<NPIX / 256, 256>>>(w, out);
}

// round 9
// speedup vs baseline: 1.2729x; 1.0036x over previous
#include <cuda_runtime.h>
#include <math.h>

// Shapes (fixed by the problem)
#define BATCH 4
#define CHN   32
#define HDIM  256
#define WDIM  256
#define PLANE (HDIM * WDIM)           // 65536
#define NPIX  (BATCH * PLANE)         // 262144
#define NROWS (BATCH * CHN * HDIM)    // 32768 rows (W pass)
#define NEL   (BATCH * CHN * PLANE)   // 8388608 complex elements

// ---------- global scratch / tables (static device memory only) ----------
__device__ float4 g_scratch4[NEL / 2];          // 8388608 float2 viewed as float4
__device__ float2 g_c1[256];
__device__ float2 g_c2[256];
__device__ float2 g_w256[256];                  // exp(-2*pi*i*m/256)
__device__ float  g_scale;

// ---------- complex helpers ----------
static __device__ __forceinline__ float2 cmul(float2 a, float2 b) {
    return make_float2(fmaf(a.x, b.x, -(a.y * b.y)), fmaf(a.x, b.y, a.y * b.x));
}
static __device__ __forceinline__ float2 cadd(float2 a, float2 b) {
    return make_float2(a.x + b.x, a.y + b.y);
}
static __device__ __forceinline__ float2 csub(float2 a, float2 b) {
    return make_float2(a.x - b.x, a.y - b.y);
}

// ---------- packed f32x2 helpers (Blackwell FFMA2 via PTX) ----------
static __device__ __forceinline__ unsigned long long pack2(float a, float b) {
    unsigned long long r;
    asm("mov.b64 %0, {%1, %2};" : "=l"(r) : "f"(a), "f"(b));
    return r;
}
static __device__ __forceinline__ void fma2(unsigned long long& d,
                                            unsigned long long a,
                                            unsigned long long b) {
    asm("fma.rn.f32x2 %0, %1, %2, %0;" : "+l"(d) : "l"(a), "l"(b));
}
static __device__ __forceinline__ void unpack2(unsigned long long v, float& a, float& b) {
    asm("mov.b64 {%0, %1}, %2;" : "=f"(a), "=f"(b) : "l"(v));
}

// ---------- register DFT-16: DIF radix-2, natural in, bit-reversed out ----------
template <int S>
static __device__ __forceinline__ void fft16(float2* r) {
    const float sg = (float)S;
    const float C16[8] = {1.0f, 0.923879533f, 0.707106781f, 0.382683432f,
                          0.0f, -0.382683432f, -0.707106781f, -0.923879533f};
    const float S16[8] = {0.0f, 0.382683432f, 0.707106781f, 0.923879533f,
                          1.0f, 0.923879533f, 0.707106781f, 0.382683432f};
#pragma unroll
    for (int j = 0; j < 8; j++) {
        float2 u = r[j], v = r[j + 8];
        float2 d = csub(u, v);
        r[j] = cadd(u, v);
        r[j + 8] = (j == 0) ? d : cmul(d, make_float2(C16[j], sg * S16[j]));
    }
    const float C8[4] = {1.0f, 0.707106781f, 0.0f, -0.707106781f};
    const float S8[4] = {0.0f, 0.707106781f, 1.0f, 0.707106781f};
#pragma unroll
    for (int b = 0; b < 16; b += 8) {
#pragma unroll
        for (int j = 0; j < 4; j++) {
            float2 u = r[b + j], v = r[b + j + 4];
            float2 d = csub(u, v);
            r[b + j] = cadd(u, v);
            r[b + j + 4] = (j == 0) ? d : cmul(d, make_float2(C8[j], sg * S8[j]));
        }
    }
#pragma unroll
    for (int b = 0; b < 16; b += 4) {
        {
            float2 u = r[b], v = r[b + 2];
            r[b] = cadd(u, v);
            r[b + 2] = csub(u, v);
        }
        {
            float2 u = r[b + 1], v = r[b + 3];
            float2 d = csub(u, v);
            r[b + 1] = cadd(u, v);
            r[b + 3] = make_float2(-sg * d.y, sg * d.x);
        }
    }
#pragma unroll
    for (int b = 0; b < 16; b += 2) {
        float2 u = r[b], v = r[b + 1];
        r[b] = cadd(u, v);
        r[b + 1] = csub(u, v);
    }
}

// 8 FFT pipelines per 128-thread block. NAT (staging) and PADX (FFT transpose)
// are SEPARATE buffers so PADX traffic stays warp-private (group g = 16 threads
// with the same tid>>4, contiguous lanes -> one warp holds groups 2w, 2w+1).
#define NAT(i, g)      ((i) * 9 + (g))                   // 256 x 8, pad 9  -> 2304
#define PADX(k1, t, g) ((g) * 272 + (k1) * 17 + (t))     // per-g 272      -> 2176

// core: nat holds u[i] = x_shift[i]*c1[i]. Produces y = ifft(fft(u)*c2) in regs:
// rout[j] = y[m], m = t + 16*brev4(j). Internal syncs are warp-scope only:
// every shared exchange is within one warp's 16-thread group. The c2 multiply
// stays in registers (thread already holds the k = t mod 16 residue class the
// inverse stage-1 needs) -> one shared round trip eliminated.
static __device__ __forceinline__ void frft_core(const float2* nat, float2* pad,
                                                 const float2* sc2, const float2* sw,
                                                 int t, int g, float2* rout) {
    const int BR[16] = {0, 8, 4, 12, 2, 10, 6, 14, 1, 9, 5, 13, 3, 11, 7, 15};
    float2 r[16];

    // ---- forward FFT stage 1 (gather from NAT; caller synced)
#pragma unroll
    for (int n1 = 0; n1 < 16; n1++) r[n1] = nat[NAT(16 * n1 + t, g)];
    fft16<-1>(r);
#pragma unroll
    for (int j = 0; j < 16; j++) {
        int k1 = BR[j];
        float2 v = r[j];
        int m = (t * k1) & 255;
        if (m) v = cmul(v, sw[m]);
        pad[PADX(k1, t, g)] = v;
    }
    __syncwarp();

    // ---- forward FFT stage 2
#pragma unroll
    for (int n2 = 0; n2 < 16; n2++) r[n2] = pad[PADX(t, n2, g)];
    __syncwarp();
    fft16<-1>(r);

    // ---- kernel chirp c2 + register bit-reverse permute (no shared round trip):
    // after stage 2 this thread holds y at k = t + 16*BR[j]; inverse stage 1
    // needs exactly the k = t (mod 16) class ordered by k2 -> r2[BR[j]] = r[j]*c2[k].
    float2 r2[16];
#pragma unroll
    for (int j = 0; j < 16; j++) r2[BR[j]] = cmul(r[j], sc2[t + 16 * BR[j]]);

    // ---- inverse FFT stage 1
    fft16<1>(r2);
#pragma unroll
    for (int j = 0; j < 16; j++) {
        int k1 = BR[j];
        float2 v = r2[j];
        int m = (t * k1) & 255;
        if (m) {
            float2 wv = sw[m];
            v = cmul(v, make_float2(wv.x, -wv.y));
        }
        pad[PADX(k1, t, g)] = v;
    }
    __syncwarp();

    // ---- inverse FFT stage 2
#pragma unroll
    for (int n2 = 0; n2 < 16; n2++) r[n2] = pad[PADX(t, n2, g)];
    fft16<1>(r);
#pragma unroll
    for (int j = 0; j < 16; j++) rout[j] = r[j];
}

// ---------- kernel 0: build chirp / twiddle tables from alpha ----------
__global__ void k_init(const float* __restrict__ alpha) {
    int i = threadIdx.x;  // 256 threads
    float a = fminf(fmaxf(alpha[0], 1e-4f), 2.0f - 1e-4f);
    float s4, c4;
    sincospif(a * 0.25f, &s4, &c4);
    float tan_a2 = s4 / c4;                 // tan(a*pi/4)
    float sin_a = sinpif(a * 0.5f);         // sin(a*pi/2)
    float n = (float)(i - 128);
    float n2 = n * n;
    float s, c;
    sincospif(-n2 * tan_a2 * (1.0f / 256.0f), &s, &c);
    g_c1[i] = make_float2(c, s);
    sincospif(-n2 / (256.0f * sin_a), &s, &c);
    g_c2[i] = make_float2(c, s);
    sincospif(-(float)i * (2.0f / 256.0f), &s, &c);
    g_w256[i] = make_float2(c, s);
    if (i == 0) g_scale = 1.0f / (256.0f * sqrtf(fabsf(sin_a) + 1e-12f));
}

// ---------- kernel 1: FRFT along W (rows). 8 rows/block, 128 threads. ----------
__global__ void __launch_bounds__(128) k_frft_w(const float* __restrict__ x) {
    __shared__ float2 nat[2304];
    __shared__ float2 pad[2176];
    __shared__ float2 sc1[256], sc2[256], sw[256];
    float2* scr = reinterpret_cast<float2*>(g_scratch4);

    int tid = threadIdx.x;
    sc1[tid] = g_c1[tid];           sc1[tid + 128] = g_c1[tid + 128];
    sc2[tid] = g_c2[tid];           sc2[tid + 128] = g_c2[tid + 128];
    sw[tid]  = g_w256[tid];         sw[tid + 128]  = g_w256[tid + 128];

    int rowbase0 = blockIdx.x * 8 * 256;
    // staging in: uses only self-written sc1 entries -> no sync yet
#pragma unroll
    for (int half = 0; half < 2; half++) {
        int i = tid + 128 * half;
        float2 c1i = sc1[i];
        int src = (i + 128) & 255;  // ifftshift
#pragma unroll
        for (int k = 0; k < 8; k++) {
            float xv = x[rowbase0 + k * 256 + src];
            nat[NAT(i, k)] = make_float2(xv * c1i.x, xv * c1i.y);
        }
    }
    __syncthreads();

    int t = tid & 15, g = tid >> 4;
    float2 r[16];
    frft_core(nat, pad, sc2, sw, t, g, r);

    // out-staging: column g of NAT is read/written only by group g (same warp),
    // ordered by program order + core's syncwarps -> no barrier needed here.
    float scale = g_scale;
    const int BR[16] = {0, 8, 4, 12, 2, 10, 6, 14, 1, 9, 5, 13, 3, 11, 7, 15};
#pragma unroll
    for (int j = 0; j < 16; j++) {
        int m = t + 16 * BR[j];
        float2 v = cmul(r[j], sc1[m]);
        nat[NAT((m + 128) & 255, g)] = make_float2(v.x * scale, v.y * scale);  // fftshift
    }
    __syncthreads();
#pragma unroll
    for (int half = 0; half < 2; half++) {
        int i = tid + 128 * half;
#pragma unroll
        for (int k = 0; k < 8; k++)
            scr[rowbase0 + k * 256 + i] = nat[NAT(i, k)];
    }
}

// ---------- kernel 2: FRFT along H (columns), in place, 8-col tiles ----------
__global__ void __launch_bounds__(128) k_frft_h() {
    __shared__ float2 nat[2304];
    __shared__ float2 pad[2176];
    __shared__ float2 sc1[256], sc2[256], sw[256];
    float2* scr = reinterpret_cast<float2*>(g_scratch4);

    int tid = threadIdx.x;
    sc1[tid] = g_c1[tid];           sc1[tid + 128] = g_c1[tid + 128];
    sc2[tid] = g_c2[tid];           sc2[tid + 128] = g_c2[tid + 128];
    sw[tid]  = g_w256[tid];         sw[tid + 128]  = g_w256[tid + 128];
    __syncthreads();  // staging reads sc1[h] cross-thread

    int plane = blockIdx.x >> 5;          // 0..127  (b*C + c)
    int w0 = (blockIdx.x & 31) * 8;       // column tile
    int pbase = plane * PLANE;

    // load 256(h) x 8(w) tile, ifftshift along h, multiply c1[h]
#pragma unroll
    for (int k = 0; k < 16; k++) {
        int e = tid + 128 * k;   // 0..2047
        int h = e >> 3, wq = e & 7;
        float2 v = scr[pbase + ((h + 128) & 255) * 256 + w0 + wq];
        nat[NAT(h, wq)] = cmul(v, sc1[h]);
    }
    __syncthreads();

    int t = tid & 15, g = tid >> 4;  // g = column within tile
    float2 r[16];
    frft_core(nat, pad, sc2, sw, t, g, r);

    float scale = g_scale;
    const int BR[16] = {0, 8, 4, 12, 2, 10, 6, 14, 1, 9, 5, 13, 3, 11, 7, 15};
#pragma unroll
    for (int j = 0; j < 16; j++) {
        int m = t + 16 * BR[j];
        float2 v = cmul(r[j], sc1[m]);
        nat[NAT((m + 128) & 255, g)] = make_float2(v.x * scale, v.y * scale);  // fftshift
    }
    __syncthreads();

    // coalesced global write-back (in place)
#pragma unroll
    for (int k = 0; k < 16; k++) {
        int e = tid + 128 * k;
        int o = e >> 3, wq = e & 7;
        scr[pbase + o * 256 + w0 + wq] = nat[NAT(o, wq)];
    }
}

// ---------- fast helpers for k_conv ----------
static __device__ __forceinline__ float fast_mag(float x, float y) {
    float z2 = fmaf(x, x, y * y);
    float rs;
    asm("rsqrt.approx.f32 %0, %1;" : "=f"(rs) : "f"(z2));
    float m = z2 * rs;
    return (z2 > 0.0f) ? m : 0.0f;
}
static __device__ __forceinline__ float fast_atan2(float y, float x) {
    float ax = fabsf(x), ay = fabsf(y);
    float mx = fmaxf(ax, ay), mn = fminf(ax, ay);
    float rc;
    asm("rcp.approx.f32 %0, %1;" : "=f"(rc) : "f"(mx));
    float t = mn * rc;
    t = (mx == 0.0f) ? 0.0f : t;
    float s = t * t;
    float p = -0.0117212f;
    p = fmaf(p, s, 0.05265332f);
    p = fmaf(p, s, -0.11643287f);
    p = fmaf(p, s, 0.19354346f);
    p = fmaf(p, s, -0.33262347f);
    p = fmaf(p, s, 0.99997726f);
    float r = t * p;
    if (ay > ax) r = 1.57079632679f - r;
    if (x < 0.0f) r = 3.14159265359f - r;
    return copysignf(r, y);
}

// ---------- kernel 3: mag/phase + 1x1 conv. 1 pixel/thread, o-pair f32x2 packing.
// If ALL phase weights are zero (true for the given w: identity on magnitude
// channels), the atan2 + phase-FMA half is skipped entirely — exact math.
__global__ void __launch_bounds__(256, 3) k_conv(const float* __restrict__ w,
                                                 float* __restrict__ out) {
    // [c][op]: packed weight pairs for output channels (2op, 2op+1)
    __shared__ unsigned long long wsm[CHN * 16];  // 4 KB
    __shared__ unsigned long long wsp[CHN * 16];  // 4 KB
    const float2* Y = reinterpret_cast<const float2*>(g_scratch4);

    const float INV_PI = 0.318309886f;
    int tid = threadIdx.x;
    int anyp = 0;
#pragma unroll
    for (int i = tid; i < CHN * 16; i += 256) {
        int c = i >> 4, op = i & 15;
        float wm0 = w[(2 * op) * 64 + c];
        float wm1 = w[(2 * op + 1) * 64 + c];
        float wp0 = w[(2 * op) * 64 + 32 + c] * INV_PI;
        float wp1 = w[(2 * op + 1) * 64 + 32 + c] * INV_PI;
        wsm[i] = pack2(wm0, wm1);
        wsp[i] = pack2(wp0, wp1);
        anyp |= (wp0 != 0.0f) | (wp1 != 0.0f);
    }
    int hasphase = __syncthreads_or(anyp);  // barrier + reduction

    int pix = blockIdx.x * 256 + tid;   // 0..262143
    int b = pix >> 16;
    int hw = pix & 65535;
    const float2* base = Y + b * (CHN * PLANE) + hw;

    unsigned long long acc[16];
#pragma unroll
    for (int op = 0; op < 16; op++) acc[op] = 0ULL;

    if (!hasphase) {
#pragma unroll 4
        for (int c = 0; c < CHN; c++) {
            float2 z = base[c * PLANE];
            float m = fast_mag(z.x, z.y);
            unsigned long long mm = pack2(m, m);
            const ulonglong2* row2 = reinterpret_cast<const ulonglong2*>(wsm + (c << 4));
#pragma unroll
            for (int q = 0; q < 8; q++) {
                ulonglong2 wv = row2[q];   // broadcast LDS.128
                fma2(acc[2 * q], wv.x, mm);
                fma2(acc[2 * q + 1], wv.y, mm);
            }
        }
    } else {
#pragma unroll 2
        for (int c = 0; c < CHN; c++) {
            float2 z = base[c * PLANE];
            float m = fast_mag(z.x, z.y);
            float ph = fast_atan2(z.y, z.x);
            unsigned long long mm = pack2(m, m);
            unsigned long long pp = pack2(ph, ph);
            const ulonglong2* rm = reinterpret_cast<const ulonglong2*>(wsm + (c << 4));
            const ulonglong2* rp = reinterpret_cast<const ulonglong2*>(wsp + (c << 4));
#pragma unroll
            for (int q = 0; q < 8; q++) {
                ulonglong2 wvm = rm[q];
                ulonglong2 wvp = rp[q];
                fma2(acc[2 * q], wvm.x, mm);
                fma2(acc[2 * q + 1], wvm.y, mm);
                fma2(acc[2 * q], wvp.x, pp);
                fma2(acc[2 * q + 1], wvp.y, pp);
            }
        }
    }

    float* ob = out + b * (CHN * PLANE) + hw;
#pragma unroll
    for (int op = 0; op < 16; op++) {
        float a0, a1;
        unpack2(acc[op], a0, a1);
        ob[(2 * op) * PLANE] = a0;
        ob[(2 * op + 1) * PLANE] = a1;
    }
}

// ---------- launcher ----------
extern "C" void kernel_launch(void* const* d_in, const int* in_sizes, int n_in,
                              void* d_out, int out_size) {
    const float* x = nullptr;
    const float* alpha = nullptr;
    const float* w = nullptr;
    for (int i = 0; i < n_in; i++) {
        if (in_sizes[i] == 1)
            alpha = (const float*)d_in[i];
        else if (in_sizes[i] == CHN * 2 * CHN)
            w = (const float*)d_in[i];
        else
            x = (const float*)d_in[i];
    }
    float* out = (float*)d_out;

    k_init<<<1, 256>>>(alpha);
    k_frft_w<<<NROWS / 8, 128>>>(x);
    k_frft_h<<<(BATCH * CHN * WDIM) / 8 , 128>>>();
    k_conv<<<NPIX / 256, 256>>>(w, out);
}